// round 3
// baseline (speedup 1.0000x reference)
#include <cuda_runtime.h>
#include <math.h>

// Problem constants (fixed shapes from reference)
#define DIM   32
#define NN    32          // neighbors per entity
#define NRELS 64
#define RP    33          // padded pitch for rel table in smem (bank-conflict avoidance)
#define BATCH 1024
#define WARPS 8
#define THREADS (WARPS * 32)

// Scratch: hop-1 updated entity vectors, [B][32 neighbors][DIM]
__device__ float g_out1[BATCH * NN * DIM];

__device__ __forceinline__ float wmax(float v) {
#pragma unroll
    for (int o = 16; o; o >>= 1) v = fmaxf(v, __shfl_xor_sync(0xffffffffu, v, o));
    return v;
}
__device__ __forceinline__ float wsum(float v) {
#pragma unroll
    for (int o = 16; o; o >>= 1) v += __shfl_xor_sync(0xffffffffu, v, o);
    return v;
}

// ---------------------------------------------------------------------------
// Kernel 1: iteration 0, hop 1.  One warp per node (b, m), node = b*32 + m.
//   e1 = adj_ent[drug[b]*32 + m]
//   sv = ent_emb[e1]; neighbors (adj_ent[e1][n], adj_rel[e1][n])
//   scores = softmax_n( sv . rel_emb[r_n] )
//   agg    = sum_n scores_n * ent_emb[e_n]
//   out1   = sigmoid( (sv+agg) @ W + b )
// ---------------------------------------------------------------------------
__global__ __launch_bounds__(THREADS)
void kgcn_hop1_kernel(const int* __restrict__ drug,
                      const int* __restrict__ adj_e,
                      const int* __restrict__ adj_r,
                      const float* __restrict__ ent,
                      const float* __restrict__ rel,
                      const float* __restrict__ W,
                      const float* __restrict__ bias,
                      int B)
{
    __shared__ float rel_s[NRELS * RP];
    __shared__ float W_s[DIM * DIM];
    __shared__ float b_s[DIM];
    __shared__ float sv_s[WARPS][32];
    __shared__ float sc_s[WARPS][32];
    __shared__ int   en_s[WARPS][32];

    const int tid = threadIdx.x;
    // Load tables into shared
    for (int i = tid; i < NRELS * DIM; i += THREADS) {
        rel_s[(i >> 5) * RP + (i & 31)] = rel[i];
    }
    for (int i = tid; i < DIM * DIM; i += THREADS) W_s[i] = W[i];
    if (tid < DIM) b_s[tid] = bias[tid];
    __syncthreads();

    const int lane = tid & 31;
    const int wl   = tid >> 5;
    float* svb = sv_s[wl];
    float* scb = sc_s[wl];
    int*   enb = en_s[wl];

    const int gwarp  = (blockIdx.x * THREADS + tid) >> 5;
    const int nwarps = (gridDim.x * THREADS) >> 5;
    const int total  = B * NN;

    for (int node = gwarp; node < total; node += nwarps) {
        const int b = node >> 5;
        const int m = node & 31;
        const int e0 = drug[b];
        const int e1 = adj_e[e0 * NN + m];

        const float sv = ent[e1 * DIM + lane];         // coalesced 128B row
        const int   en = adj_e[e1 * NN + lane];        // lane = neighbor n
        const int   rr = adj_r[e1 * NN + lane];

        __syncwarp();
        svb[lane] = sv;
        enb[lane] = en;
        __syncwarp();

        // attention score for neighbor n = lane
        float s = 0.f;
#pragma unroll
        for (int d = 0; d < DIM; d++) s += svb[d] * rel_s[rr * RP + d];

        // softmax over neighbors (across the warp)
        const float mx = wmax(s);
        const float ex = expf(s - mx);
        const float sm = wsum(ex);
        scb[lane] = ex / sm;
        __syncwarp();

        // aggregate neighbor embeddings: lane = feature dim d
        float a = 0.f;
#pragma unroll
        for (int n = 0; n < NN; n++)
            a += scb[n] * ent[enb[n] * DIM + lane];    // broadcast row, coalesced

        const float h = sv + a;
        __syncwarp();
        svb[lane] = h;
        __syncwarp();

        float o = b_s[lane];
#pragma unroll
        for (int d = 0; d < DIM; d++) o += svb[d] * W_s[d * DIM + lane];

        const float out = 1.f / (1.f + expf(-o));      // sigmoid (iter 0)
        g_out1[node * DIM + lane] = out;
        __syncwarp();
    }
}

// ---------------------------------------------------------------------------
// Kernel 2: iteration 0 hop 0  +  iteration 1 (final).  One warp per b.
// Both steps use the SAME relation rows adj_rel[e0][n] for attention.
// ---------------------------------------------------------------------------
__global__ __launch_bounds__(THREADS)
void kgcn_final_kernel(const int* __restrict__ drug,
                       const int* __restrict__ adj_e,
                       const int* __restrict__ adj_r,
                       const float* __restrict__ ent,
                       const float* __restrict__ rel,
                       const float* __restrict__ W,
                       const float* __restrict__ bias,
                       float* __restrict__ out,
                       int B)
{
    __shared__ float rel_s[NRELS * RP];
    __shared__ float W_s[DIM * DIM];
    __shared__ float b_s[DIM];
    __shared__ float sv_s[WARPS][32];
    __shared__ float sc_s[WARPS][32];
    __shared__ int   en_s[WARPS][32];

    const int tid = threadIdx.x;
    for (int i = tid; i < NRELS * DIM; i += THREADS) {
        rel_s[(i >> 5) * RP + (i & 31)] = rel[i];
    }
    for (int i = tid; i < DIM * DIM; i += THREADS) W_s[i] = W[i];
    if (tid < DIM) b_s[tid] = bias[tid];
    __syncthreads();

    const int lane = tid & 31;
    const int wl   = tid >> 5;
    float* svb = sv_s[wl];
    float* scb = sc_s[wl];
    int*   enb = en_s[wl];

    const int gwarp  = (blockIdx.x * THREADS + tid) >> 5;
    const int nwarps = (gridDim.x * THREADS) >> 5;

    for (int b = gwarp; b < B; b += nwarps) {
        const int e0 = drug[b];

        const float sv = ent[e0 * DIM + lane];
        const int   en = adj_e[e0 * NN + lane];
        const int   rr = adj_r[e0 * NN + lane];

        __syncwarp();
        svb[lane] = sv;
        enb[lane] = en;
        __syncwarp();

        // ---- iteration 0, hop 0 (sigmoid), neighbors = raw ent_emb ----
        float s = 0.f;
#pragma unroll
        for (int d = 0; d < DIM; d++) s += svb[d] * rel_s[rr * RP + d];
        float mx = wmax(s);
        float ex = expf(s - mx);
        float sm = wsum(ex);
        scb[lane] = ex / sm;
        __syncwarp();

        float a = 0.f;
#pragma unroll
        for (int n = 0; n < NN; n++)
            a += scb[n] * ent[enb[n] * DIM + lane];

        float h = sv + a;
        __syncwarp();
        svb[lane] = h;
        __syncwarp();

        float o = b_s[lane];
#pragma unroll
        for (int d = 0; d < DIM; d++) o += svb[d] * W_s[d * DIM + lane];
        const float v0 = 1.f / (1.f + expf(-o));       // out0[b][lane]

        // ---- iteration 1 (tanh): self = v0, neighbors = g_out1, same relations ----
        __syncwarp();
        svb[lane] = v0;
        __syncwarp();

        float s2 = 0.f;
#pragma unroll
        for (int d = 0; d < DIM; d++) s2 += svb[d] * rel_s[rr * RP + d];
        mx = wmax(s2);
        ex = expf(s2 - mx);
        sm = wsum(ex);
        scb[lane] = ex / sm;
        __syncwarp();

        float a2 = 0.f;
        const float* o1 = &g_out1[b * NN * DIM];
#pragma unroll
        for (int n = 0; n < NN; n++)
            a2 += scb[n] * o1[n * DIM + lane];

        const float h2 = v0 + a2;
        __syncwarp();
        svb[lane] = h2;
        __syncwarp();

        float o2 = b_s[lane];
#pragma unroll
        for (int d = 0; d < DIM; d++) o2 += svb[d] * W_s[d * DIM + lane];

        out[b * DIM + lane] = tanhf(o2);
        __syncwarp();
    }
}

extern "C" void kernel_launch(void* const* d_in, const int* in_sizes, int n_in,
                              void* d_out, int out_size)
{
    const int*   drug  = (const int*)  d_in[0];  // [B]
    const int*   adj_e = (const int*)  d_in[1];  // [NUM_ENT, 32]
    const int*   adj_r = (const int*)  d_in[2];  // [NUM_ENT, 32]
    const float* ent   = (const float*)d_in[3];  // [NUM_ENT, 32]
    const float* rel   = (const float*)d_in[4];  // [64, 32]
    const float* W     = (const float*)d_in[5];  // [32, 32]
    const float* bias  = (const float*)d_in[6];  // [32]
    float* out = (float*)d_out;

    const int B = in_sizes[0];

    // Kernel 1: B*32 nodes, warp per node, grid-stride (~4 nodes/warp at B=1024)
    kgcn_hop1_kernel<<<1024, THREADS>>>(drug, adj_e, adj_r, ent, rel, W, bias, B);

    // Kernel 2: warp per batch element
    int blocks2 = (B + WARPS - 1) / WARPS;
    kgcn_final_kernel<<<blocks2, THREADS>>>(drug, adj_e, adj_r, ent, rel, W, bias, out, B);
}

// round 6
// speedup vs baseline: 1.2153x; 1.2153x over previous
#include <cuda_runtime.h>
#include <math.h>

// Fixed problem shapes
#define DIM   32
#define NN    32          // neighbors per entity
#define NRELS 64
#define RP    33          // padded pitch for rel table in smem
#define TPB   1024        // 32 warps = 32 hop-1 nodes per batch element

__device__ __forceinline__ float wmax(float v) {
#pragma unroll
    for (int o = 16; o; o >>= 1) v = fmaxf(v, __shfl_xor_sync(0xffffffffu, v, o));
    return v;
}
__device__ __forceinline__ float wsum(float v) {
#pragma unroll
    for (int o = 16; o; o >>= 1) v += __shfl_xor_sync(0xffffffffu, v, o);
    return v;
}

// ---------------------------------------------------------------------------
// Fused KGCN: one block per batch element.
//   Phase A (32 warps, depth 1): hop-1 nodes m=0..31
//       e1 = adj_ent[e0][m]; out1[m] = sigmoid((sv + att-agg(ent)) @ W + b)
//     Warp 0 additionally computes hop-0:  v0 = sigmoid((sv0 + att-agg(ent)) @ W + b)
//   __syncthreads()
//   Phase B (warp 0): iteration 1:  out = tanh((v0 + att-agg(out1)) @ W + b)
// Attention: scores = softmax_n( self . rel_emb[adj_rel[e][n]] )
// ---------------------------------------------------------------------------
__global__ __launch_bounds__(TPB)
void kgcn_fused_kernel(const int* __restrict__ drug,
                       const int* __restrict__ adj_e,
                       const int* __restrict__ adj_r,
                       const float* __restrict__ ent,
                       const float* __restrict__ rel,
                       const float* __restrict__ W,
                       const float* __restrict__ bias,
                       float* __restrict__ out)
{
    __shared__ float rel_s[NRELS * RP];     // 8448 B
    __shared__ float W_s[DIM * DIM];        // 4096 B  W_s[d][j]
    __shared__ float b_s[DIM];
    __shared__ float out1[NN * DIM];        // hop-1 results   4096 B
    __shared__ float v0_s[DIM];
    __shared__ float sv_s[32][32];          // per-warp self vector
    __shared__ float sc_s[32][32];          // per-warp softmax scores
    __shared__ int   en_s[32][32];          // per-warp neighbor ids

    const int tid  = threadIdx.x;
    const int lane = tid & 31;
    const int w    = tid >> 5;              // warp id == hop-1 node index m

    // ---- load tables into shared ----
    for (int i = tid; i < NRELS * DIM; i += TPB)
        rel_s[(i >> 5) * RP + (i & 31)] = rel[i];
    for (int i = tid; i < DIM * DIM; i += TPB) W_s[i] = W[i];
    if (tid < DIM) b_s[tid] = bias[tid];
    __syncthreads();

    const int b  = blockIdx.x;
    const int e0 = drug[b];

    float* svb = sv_s[w];
    float* scb = sc_s[w];
    int*   enb = en_s[w];

    // =================== Phase A: hop-1 node m = w ===================
    {
        const int e1 = adj_e[e0 * NN + w];

        const float sv = ent[e1 * DIM + lane];       // coalesced row
        const int   en = adj_e[e1 * NN + lane];      // lane = neighbor n
        const int   rr = adj_r[e1 * NN + lane];

        svb[lane] = sv;
        enb[lane] = en;
        __syncwarp();

        // attention score for neighbor n = lane
        float s = 0.f;
#pragma unroll
        for (int d = 0; d < DIM; d++) s += svb[d] * rel_s[rr * RP + d];

        const float mx = wmax(s);
        const float ex = __expf(s - mx);
        const float sm = wsum(ex);
        scb[lane] = ex / sm;
        __syncwarp();

        // weighted aggregate of neighbor embeddings; lane = feature dim
        float a = 0.f;
#pragma unroll
        for (int n = 0; n < NN; n++)
            a += scb[n] * ent[enb[n] * DIM + lane];

        const float h = sv + a;
        __syncwarp();
        svb[lane] = h;
        __syncwarp();

        float o = b_s[lane];
#pragma unroll
        for (int d = 0; d < DIM; d++) o += svb[d] * W_s[d * DIM + lane];

        out1[w * DIM + lane] = 1.f / (1.f + __expf(-o));   // sigmoid
    }

    // ---- warp 0 also computes hop-0 v0 (independent of hop-1 results) ----
    if (w == 0) {
        const float sv = ent[e0 * DIM + lane];
        const int   en = adj_e[e0 * NN + lane];
        const int   rr = adj_r[e0 * NN + lane];

        __syncwarp();
        svb[lane] = sv;
        enb[lane] = en;
        __syncwarp();

        float s = 0.f;
#pragma unroll
        for (int d = 0; d < DIM; d++) s += svb[d] * rel_s[rr * RP + d];

        const float mx = wmax(s);
        const float ex = __expf(s - mx);
        const float sm = wsum(ex);
        scb[lane] = ex / sm;
        __syncwarp();

        float a = 0.f;
#pragma unroll
        for (int n = 0; n < NN; n++)
            a += scb[n] * ent[enb[n] * DIM + lane];

        const float h = sv + a;
        __syncwarp();
        svb[lane] = h;
        __syncwarp();

        float o = b_s[lane];
#pragma unroll
        for (int d = 0; d < DIM; d++) o += svb[d] * W_s[d * DIM + lane];

        v0_s[lane] = 1.f / (1.f + __expf(-o));
    }

    __syncthreads();

    // =================== Phase B: iteration 1 (warp 0) ===================
    if (w == 0) {
        const float v0 = v0_s[lane];
        const int   rr = adj_r[e0 * NN + lane];      // same relation rows as hop-0

        __syncwarp();
        svb[lane] = v0;
        __syncwarp();

        float s = 0.f;
#pragma unroll
        for (int d = 0; d < DIM; d++) s += svb[d] * rel_s[rr * RP + d];

        const float mx = wmax(s);
        const float ex = __expf(s - mx);
        const float sm = wsum(ex);
        scb[lane] = ex / sm;
        __syncwarp();

        // neighbors are the hop-1 outputs in shared memory
        float a = 0.f;
#pragma unroll
        for (int n = 0; n < NN; n++)
            a += scb[n] * out1[n * DIM + lane];

        const float h = v0 + a;
        __syncwarp();
        svb[lane] = h;
        __syncwarp();

        float o = b_s[lane];
#pragma unroll
        for (int d = 0; d < DIM; d++) o += svb[d] * W_s[d * DIM + lane];

        out[b * DIM + lane] = tanhf(o);
    }
}

extern "C" void kernel_launch(void* const* d_in, const int* in_sizes, int n_in,
                              void* d_out, int out_size)
{
    const int*   drug  = (const int*)  d_in[0];  // [B]
    const int*   adj_e = (const int*)  d_in[1];  // [NUM_ENT, 32]
    const int*   adj_r = (const int*)  d_in[2];  // [NUM_ENT, 32]
    const float* ent   = (const float*)d_in[3];  // [NUM_ENT, 32]
    const float* rel   = (const float*)d_in[4];  // [64, 32]
    const float* W     = (const float*)d_in[5];  // [32, 32]
    const float* bias  = (const float*)d_in[6];  // [32]
    float* out = (float*)d_out;

    const int B = in_sizes[0];
    kgcn_fused_kernel<<<B, TPB>>>(drug, adj_e, adj_r, ent, rel, W, bias, out);
}